// round 4
// baseline (speedup 1.0000x reference)
#include <cuda_runtime.h>
#include <cuda_fp16.h>
#include <cstdint>

#define EDIM    512
#define FDIM    2048
#define QDIM    8
#define NCHUNK  32          // K chunks of 64
#define NTOKB   256         // 32768 / 128

// ---- device scratch ----
__device__ __align__(128) unsigned char g_w2s[4 * NCHUNK * 16384];   // 2 MB: [nb][c][128n x 64k fp16, SW128]
__device__ __align__(128) unsigned char g_w1b1[73728];               // W1 pairs 64KB + b1 pairs 8KB
__device__ __align__(128) unsigned char g_h[NTOKB * NCHUNK * 16384]; // 128 MB: [tb][c][128m x 64k fp16, SW128]

#define SWZ(o) ((o) ^ (((o) >> 3) & 0x70))

__device__ __forceinline__ uint32_t smem_u32(const void* p) {
    uint32_t a;
    asm("{ .reg .u64 t; cvta.to.shared.u64 t, %1; cvt.u32.u64 %0, t; }" : "=r"(a) : "l"(p));
    return a;
}
#define MBAR_INIT(a, c) asm volatile("mbarrier.init.shared.b64 [%0], %1;" :: "r"(a), "r"((uint32_t)(c)) : "memory")
#define MBAR_EXPECT(a, n) asm volatile("mbarrier.arrive.expect_tx.shared.b64 _, [%0], %1;" :: "r"(a), "r"((uint32_t)(n)) : "memory")
#define MBAR_ARRIVE(a) asm volatile("mbarrier.arrive.shared.b64 _, [%0];" :: "r"(a) : "memory")
#define MBAR_WAIT(a, ph) do { \
    uint32_t _m = (a), _p = (ph), _d; \
    asm volatile("{ .reg .pred p; mbarrier.try_wait.parity.acquire.cta.shared::cta.b64 p, [%1], %2; selp.b32 %0,1,0,p; }" \
        : "=r"(_d) : "r"(_m), "r"(_p) : "memory"); \
    if (!_d) { \
        asm volatile("{ .reg .pred P1;\nWL_%=:\n mbarrier.try_wait.parity.acquire.cta.shared::cta.b64 P1, [%0], %1, 0x989680;\n @P1 bra.uni WD_%=;\n bra.uni WL_%=;\nWD_%=:\n }" \
            :: "r"(_m), "r"(_p) : "memory"); \
    } } while (0)

__device__ __forceinline__ void bulk_g2s(uint32_t dst, const void* src, uint32_t bytes, uint32_t mbar) {
    asm volatile("cp.async.bulk.shared::cluster.global.mbarrier::complete_tx::bytes [%0], [%1], %2, [%3];"
        :: "r"(dst), "l"(src), "r"(bytes), "r"(mbar) : "memory");
}
__device__ __forceinline__ void bulk_s2g(void* dst, uint32_t src, uint32_t bytes) {
    asm volatile("cp.async.bulk.global.shared::cta.bulk_group [%0], [%1], %2;"
        :: "l"(dst), "r"(src), "r"(bytes) : "memory");
}
#define BULK_COMMIT() asm volatile("cp.async.bulk.commit_group;" ::: "memory")
#define BULK_WAIT(n)  asm volatile("cp.async.bulk.wait_group %0;" :: "n"(n) : "memory")
#define FENCE_ASYNC() asm volatile("fence.proxy.async.shared::cta;" ::: "memory")

#define LDS64(v, a)  asm("ld.shared.b64 %0, [%1];" : "=l"(v) : "r"(a))
#define STS128(a, r0, r1, r2, r3) asm volatile("st.shared.v4.b32 [%0], {%1,%2,%3,%4};" :: "r"(a), "r"(r0), "r"(r1), "r"(r2), "r"(r3) : "memory")
#define FMA2(d, a, b, c) asm("fma.rn.f32x2 %0, %1, %2, %3;" : "=l"(d) : "l"(a), "l"(b), "l"(c))
#define PACK2(d, x)      asm("mov.b64 %0, {%1, %1};" : "=l"(d) : "r"(x))
#define UNPK2(lo, hi, v) asm("mov.b64 {%0, %1}, %2;" : "=r"(lo), "=r"(hi) : "l"(v))

#define LDMX4(r, a) asm volatile( \
    "ldmatrix.sync.aligned.m8n8.x4.shared.b16 {%0,%1,%2,%3}, [%4];" \
    : "=r"((r)[0]), "=r"((r)[1]), "=r"((r)[2]), "=r"((r)[3]) : "r"(a))
#define MMA16816(cf, a, b0, b1) asm volatile( \
    "mma.sync.aligned.m16n8k16.row.col.f32.f16.f16.f32 " \
    "{%0,%1,%2,%3}, {%4,%5,%6,%7}, {%8,%9}, {%0,%1,%2,%3};" \
    : "+f"((cf)[0]), "+f"((cf)[1]), "+f"((cf)[2]), "+f"((cf)[3]) \
    : "r"((a)[0]), "r"((a)[1]), "r"((a)[2]), "r"((a)[3]), "r"(b0), "r"(b1))

// ---------------- prep: W2 -> fp16 swizzled blocks ----------------
__global__ void prep_w2(const float* __restrict__ W2) {
    int idx = blockIdx.x * 256 + threadIdx.x;          // 512 n x 256 groups-of-8k
    if (idx >= 512 * 256) return;
    int n = idx >> 8, g = idx & 255;
    int k0 = g * 8;
    int nb = n >> 7, nl = n & 127;
    int c = k0 >> 6, kl = k0 & 63;
    const float* s = W2 + (size_t)n * FDIM + k0;
    float4 a = *(const float4*)s;
    float4 b = *(const float4*)(s + 4);
    __half2 p0 = __floats2half2_rn(a.x, a.y);
    __half2 p1 = __floats2half2_rn(a.z, a.w);
    __half2 p2 = __floats2half2_rn(b.x, b.y);
    __half2 p3 = __floats2half2_rn(b.z, b.w);
    uint4 v;
    v.x = *reinterpret_cast<uint32_t*>(&p0);
    v.y = *reinterpret_cast<uint32_t*>(&p1);
    v.z = *reinterpret_cast<uint32_t*>(&p2);
    v.w = *reinterpret_cast<uint32_t*>(&p3);
    uint32_t rel = (uint32_t)(nl * 128 + kl * 2);
    *(uint4*)(g_w2s + ((size_t)(nb * NCHUNK + c) << 14) + SWZ(rel)) = v;
}

// ---------------- prep: W1/b1 paired layout ----------------
__global__ void prep_w1b1(const float* __restrict__ W1, const float* __restrict__ b1) {
    int idx = blockIdx.x * 256 + threadIdx.x;
    if (idx < 8192) {                 // 1024 f-pairs x 8 j
        int p = idx >> 3, j = idx & 7;
        float2 v;
        v.x = W1[16 * p + j];
        v.y = W1[16 * p + 8 + j];
        *(float2*)(g_w1b1 + p * 64 + j * 8) = v;
    } else if (idx < 9216) {          // 1024 b1 pairs
        int i = idx - 8192;
        float2 v;
        v.x = b1[2 * i];
        v.y = b1[2 * i + 1];
        *(float2*)(g_w1b1 + 65536 + i * 8) = v;
    }
}

// ---------------- kernel A: h = relu(q.W1^T + b1) -> fp16 swizzled tiles ----------------
#define SA_MBAR 73728
#define SA_HT   73792
#define SMEM_A  (SA_HT + 2 * 16384)

__global__ void __launch_bounds__(256)
ffq_h(const float* __restrict__ x, const float* __restrict__ theta) {
    extern __shared__ char smem[];
    const uint32_t sb = smem_u32(smem);
    const int tid = threadIdx.x, wid = tid >> 5, lane = tid & 31;
    const int tb = blockIdx.x;

    if (tid == 0) MBAR_INIT(sb + SA_MBAR, 1);
    __syncthreads();
    if (tid == 0) {
        MBAR_EXPECT(sb + SA_MBAR, 73728);
        bulk_g2s(sb, g_w1b1, 73728, sb + SA_MBAR);
    }

    // q[r][j] = cos(x)*cos(theta), packed {q,q}; tokens: tb*128 + r*32 + lane
    unsigned long long q2[4][8];
    float cth[8];
#pragma unroll
    for (int j = 0; j < 8; ++j) cth[j] = __cosf(__ldg(theta + j));
#pragma unroll
    for (int r = 0; r < 4; ++r) {
        const int tok = tb * 128 + r * 32 + lane;
        float4 xa = *(const float4*)(x + (size_t)tok * EDIM);
        float4 xb = *(const float4*)(x + (size_t)tok * EDIM + 4);
        float xv[8] = {xa.x, xa.y, xa.z, xa.w, xb.x, xb.y, xb.z, xb.w};
#pragma unroll
        for (int j = 0; j < 8; ++j)
            PACK2(q2[r][j], __float_as_uint(__cosf(xv[j]) * cth[j]));
    }

    MBAR_WAIT(sb + SA_MBAR, 0);
    __syncthreads();

    const __half2 hzero = __float2half2_rn(0.0f);
    for (int c = 0; c < NCHUNK; ++c) {
        const uint32_t hbase = sb + SA_HT + (c & 1) * 16384;
        if (c >= 2) {
            if (tid == 0) BULK_WAIT(1);
            __syncthreads();
        }
        const uint32_t prb = (uint32_t)(c * 32 + wid * 4);   // pair index base
        uint32_t hv[4][4];
#pragma unroll
        for (int e = 0; e < 4; ++e) {
            unsigned long long bp, wp[8];
            LDS64(bp, sb + 65536 + (prb + e) * 8);
            const uint32_t wb = sb + (prb + e) * 64;
#pragma unroll
            for (int j = 0; j < 8; ++j) LDS64(wp[j], wb + j * 8);
#pragma unroll
            for (int r = 0; r < 4; ++r) {
                unsigned long long acc = bp;
#pragma unroll
                for (int j = 0; j < 8; ++j) FMA2(acc, q2[r][j], wp[j], acc);
                uint32_t lo, hi;
                UNPK2(lo, hi, acc);
                __half2 hh = __hmax2(__floats2half2_rn(__uint_as_float(lo), __uint_as_float(hi)), hzero);
                hv[r][e] = *reinterpret_cast<uint32_t*>(&hh);
            }
        }
#pragma unroll
        for (int r = 0; r < 4; ++r) {
            const uint32_t rel = (uint32_t)((r * 32 + lane) * 128 + wid * 16);
            STS128(hbase + SWZ(rel), hv[r][0], hv[r][1], hv[r][2], hv[r][3]);
        }
        __syncthreads();
        if (tid == 0) {
            FENCE_ASYNC();
            bulk_s2g(g_h + ((size_t)(tb * NCHUNK + c) << 14), hbase, 16384);
            BULK_COMMIT();
        }
    }
    if (tid == 0) BULK_WAIT(0);
}

// ---------------- kernel B: out = h @ W2^T + b2 (HMMA) ----------------
#define SB_FULL 98304
#define SB_CONS 98328
#define SMEM_B  98368

__global__ void __launch_bounds__(256, 2)
ffq_gemm(const float* __restrict__ b2, float* __restrict__ out) {
    extern __shared__ char smem[];
    const uint32_t sb = smem_u32(smem);
    const int tid = threadIdx.x, wid = tid >> 5, lane = tid & 31;
    const int nb = blockIdx.x, tb = blockIdx.y;
    const int wm = wid & 1, wn = wid >> 1;

    if (tid == 0) {
#pragma unroll
        for (int s = 0; s < 3; ++s) {
            MBAR_INIT(sb + SB_FULL + s * 8, 1);
            MBAR_INIT(sb + SB_CONS + s * 8, 8);
        }
    }
    __syncthreads();

    if (tid == 0) {
#pragma unroll
        for (int s = 0; s < 3; ++s) {
            MBAR_EXPECT(sb + SB_FULL + s * 8, 32768);
            bulk_g2s(sb + s * 32768, g_h + ((size_t)(tb * NCHUNK + s) << 14), 16384, sb + SB_FULL + s * 8);
            bulk_g2s(sb + s * 32768 + 16384, g_w2s + ((size_t)(nb * NCHUNK + s) << 14), 16384, sb + SB_FULL + s * 8);
        }
    }

    float cf[16][4];
#pragma unroll
    for (int f = 0; f < 16; ++f)
#pragma unroll
        for (int i = 0; i < 4; ++i) cf[f][i] = 0.0f;

    int buf = 0, ph = 0;                  // buf = c%3, ph = (c/3)&1
    for (int c = 0; c < NCHUNK; ++c) {
        MBAR_WAIT(sb + SB_FULL + buf * 8, ph);
        const uint32_t abase = sb + buf * 32768;
        const uint32_t bbase = abase + 16384;

        const uint32_t arow = (uint32_t)(wm * 64 + (lane & 15));
        const uint32_t abyte = (uint32_t)((lane >> 4) * 16);
        const uint32_t brow = (uint32_t)(wn * 32 + (lane & 7) + ((lane >> 4) & 1) * 8);
        const uint32_t bbyte = (uint32_t)(((lane >> 3) & 1) * 16);
#pragma unroll
        for (int k = 0; k < 4; ++k) {
            uint32_t af[4][4], bf[2][4];
#pragma unroll
            for (int mi = 0; mi < 4; ++mi)
                LDMX4(af[mi], abase + SWZ((arow + mi * 16) * 128 + k * 32 + abyte));
#pragma unroll
            for (int bi = 0; bi < 2; ++bi)
                LDMX4(bf[bi], bbase + SWZ((brow + bi * 16) * 128 + k * 32 + bbyte));
#pragma unroll
            for (int mi = 0; mi < 4; ++mi)
#pragma unroll
                for (int ni = 0; ni < 4; ++ni)
                    MMA16816(cf[mi * 4 + ni], af[mi], bf[ni >> 1][(ni & 1) * 2], bf[ni >> 1][(ni & 1) * 2 + 1]);
        }
        if (lane == 0) MBAR_ARRIVE(sb + SB_CONS + buf * 8);

        if (tid == 0 && c + 3 < NCHUNK) {
            const int s = c + 3;          // reuses buffer buf
            MBAR_WAIT(sb + SB_CONS + buf * 8, ph);
            MBAR_EXPECT(sb + SB_FULL + buf * 8, 32768);
            bulk_g2s(sb + buf * 32768, g_h + ((size_t)(tb * NCHUNK + s) << 14), 16384, sb + SB_FULL + buf * 8);
            bulk_g2s(sb + buf * 32768 + 16384, g_w2s + ((size_t)(nb * NCHUNK + s) << 14), 16384, sb + SB_FULL + buf * 8);
        }
        if (++buf == 3) { buf = 0; ph ^= 1; }
    }

    // epilogue
    const int rowbase = tb * 128 + wm * 64 + (lane >> 2);
    const int colbase = nb * 128 + wn * 32 + (lane & 3) * 2;
#pragma unroll
    for (int mi = 0; mi < 4; ++mi) {
#pragma unroll
        for (int ni = 0; ni < 4; ++ni) {
            const int f = mi * 4 + ni;
            const int col = colbase + ni * 8;
            const float2 bv = *(const float2*)(b2 + col);
            const int r0 = rowbase + mi * 16;
            float2 o0, o1;
            o0.x = cf[f][0] + bv.x; o0.y = cf[f][1] + bv.y;
            o1.x = cf[f][2] + bv.x; o1.y = cf[f][3] + bv.y;
            *(float2*)(out + (size_t)r0 * EDIM + col) = o0;
            *(float2*)(out + (size_t)(r0 + 8) * EDIM + col) = o1;
        }
    }
}

extern "C" void kernel_launch(void* const* d_in, const int* in_sizes, int n_in,
                              void* d_out, int out_size) {
    const float* x     = (const float*)d_in[0];
    const float* theta = (const float*)d_in[1];
    const float* W1    = (const float*)d_in[2];
    const float* b1    = (const float*)d_in[3];
    const float* W2    = (const float*)d_in[4];
    const float* b2    = (const float*)d_in[5];
    float* out = (float*)d_out;

    cudaFuncSetAttribute(ffq_h, cudaFuncAttributeMaxDynamicSharedMemorySize, SMEM_A);
    cudaFuncSetAttribute(ffq_gemm, cudaFuncAttributeMaxDynamicSharedMemorySize, SMEM_B);

    prep_w2<<<512, 256>>>(W2);
    prep_w1b1<<<36, 256>>>(W1, b1);
    ffq_h<<<NTOKB, 256, SMEM_A>>>(x, theta);
    ffq_gemm<<<dim3(4, NTOKB), 256, SMEM_B>>>(b2, out);
}